// round 1
// baseline (speedup 1.0000x reference)
#include <cuda_runtime.h>
#include <math.h>

#define B_ 4
#define L_ 4096
#define D_ 1024
#define M_ (B_*L_)            // 16384 rows
#define TOT (M_*D_)           // 16777216 elements per tensor
#define NCHUNK 32
#define CLEN (L_/NCHUNK)      // 128

// ---- scratch (device globals: no runtime allocation allowed) ----
__device__ float g_norm [TOT];
__device__ float g_alpha[TOT];
__device__ float g_beta [TOT];
__device__ float g_h    [TOT];
__device__ float g_Aprod[B_*NCHUNK*D_];
__device__ float g_hend [B_*NCHUNK*D_];
__device__ float g_carry[B_*NCHUNK*D_];

__device__ __forceinline__ float sigmoidf_(float z) { return 1.f / (1.f + expf(-z)); }
__device__ __forceinline__ float siluf_(float z)    { return z   / (1.f + expf(-z)); }

// ---------------------------------------------------------------------------
// RMS norm: one block (256 thr) per row of 1024
// ---------------------------------------------------------------------------
__global__ void rms_kernel(const float* __restrict__ ctx, const float* __restrict__ g) {
    int row = blockIdx.x;
    const float* x = ctx + (size_t)row * D_;
    float s = 0.f;
    #pragma unroll
    for (int i = threadIdx.x; i < D_; i += 256) { float v = x[i]; s += v * v; }
    __shared__ float red[8];
    #pragma unroll
    for (int o = 16; o > 0; o >>= 1) s += __shfl_xor_sync(0xffffffffu, s, o);
    if ((threadIdx.x & 31) == 0) red[threadIdx.x >> 5] = s;
    __syncthreads();
    if (threadIdx.x < 8) {
        float t = red[threadIdx.x];
        #pragma unroll
        for (int o = 4; o > 0; o >>= 1) t += __shfl_xor_sync(0xffu, t, o);
        if (threadIdx.x == 0) red[0] = t;
    }
    __syncthreads();
    float inv = rsqrtf(red[0] * (1.f / D_) + 1e-6f);
    float* y = g_norm + (size_t)row * D_;
    for (int i = threadIdx.x; i < D_; i += 256) y[i] = x[i] * inv * g[i];
}

// ---------------------------------------------------------------------------
// GEMM 1+2 fused over the N axis (N'=2048): alpha = sigmoid(norm@Wa+ba),
// beta = silu(norm@Wb+bb). Classic 128x128 block tile, 8x8 per thread.
// ---------------------------------------------------------------------------
__global__ __launch_bounds__(256) void gemm_ab_kernel(
    const float* __restrict__ Wa, const float* __restrict__ Wb,
    const float* __restrict__ ba, const float* __restrict__ bb)
{
    __shared__ float As[16][128];
    __shared__ float Bs[16][128];
    const int n0 = blockIdx.x * 128;          // [0,2048)
    const int m0 = blockIdx.y * 128;
    const bool isAlpha = (n0 < D_);
    const float* W    = isAlpha ? Wa : Wb;
    const float* bias = isAlpha ? ba : bb;
    const int ncol0   = isAlpha ? n0 : (n0 - D_);

    const int tid = threadIdx.x;
    const int tx = tid & 15, ty = tid >> 4;

    float acc[8][8];
    #pragma unroll
    for (int i = 0; i < 8; i++)
        #pragma unroll
        for (int j = 0; j < 8; j++) acc[i][j] = 0.f;

    for (int k0 = 0; k0 < D_; k0 += 16) {
        #pragma unroll
        for (int i = 0; i < 2; i++) {                 // A tile: 128x16
            int idx = tid + i * 256;
            int r = idx >> 2, c4 = idx & 3;
            float4 va = *(const float4*)(g_norm + (size_t)(m0 + r) * D_ + k0 + c4 * 4);
            As[c4*4+0][r] = va.x; As[c4*4+1][r] = va.y;
            As[c4*4+2][r] = va.z; As[c4*4+3][r] = va.w;
        }
        #pragma unroll
        for (int i = 0; i < 2; i++) {                 // B tile: 16x128
            int idx = tid + i * 256;
            int r = idx >> 5, c4 = idx & 31;
            *(float4*)&Bs[r][c4*4] = *(const float4*)(W + (size_t)(k0 + r) * D_ + ncol0 + c4 * 4);
        }
        __syncthreads();
        #pragma unroll
        for (int k = 0; k < 16; k++) {
            float ar[8], br[8];
            #pragma unroll
            for (int i = 0; i < 8; i++) ar[i] = As[k][ty * 8 + i];
            #pragma unroll
            for (int j = 0; j < 8; j++) br[j] = Bs[k][tx * 8 + j];
            #pragma unroll
            for (int i = 0; i < 8; i++)
                #pragma unroll
                for (int j = 0; j < 8; j++) acc[i][j] = fmaf(ar[i], br[j], acc[i][j]);
        }
        __syncthreads();
    }
    #pragma unroll
    for (int i = 0; i < 8; i++) {
        int m = m0 + ty * 8 + i;
        #pragma unroll
        for (int j = 0; j < 8; j++) {
            int n = ncol0 + tx * 8 + j;
            float z = acc[i][j] + bias[n];
            if (isAlpha) g_alpha[(size_t)m * D_ + n] = sigmoidf_(z);
            else         g_beta [(size_t)m * D_ + n] = siluf_(z);
        }
    }
}

// ---------------------------------------------------------------------------
// Chunked scan (3 passes). h_t = a_t*h_{t-1} + x_t, x = v*beta*sqrt(clip(1-a^2))
// ---------------------------------------------------------------------------
__global__ void scan1_kernel(const float* __restrict__ v) {
    int d = blockIdx.x * blockDim.x + threadIdx.x;
    int c = blockIdx.y, b = blockIdx.z;
    size_t base = ((size_t)b * L_ + (size_t)c * CLEN) * D_ + d;
    float h = 0.f, A = 1.f;
    for (int t = 0; t < CLEN; t++) {
        size_t idx = base + (size_t)t * D_;
        float a  = g_alpha[idx];
        float ws = sqrtf(fmaxf(1.f - a * a, 1e-6f));
        float x  = v[idx] * g_beta[idx] * ws;
        h = fmaf(a, h, x);
        A *= a;
        g_h[idx] = h;
    }
    int sidx = (b * NCHUNK + c) * D_ + d;
    g_hend[sidx] = h; g_Aprod[sidx] = A;
}

__global__ void scan2_kernel() {
    int d = threadIdx.x, b = blockIdx.x;
    float carry = 0.f;
    for (int c = 0; c < NCHUNK; c++) {
        int sidx = (b * NCHUNK + c) * D_ + d;
        g_carry[sidx] = carry;
        carry = g_Aprod[sidx] * carry + g_hend[sidx];
    }
}

__global__ void scan3_kernel() {
    if (blockIdx.y == 0) return;   // chunk 0: carry is zero
    int d = blockIdx.x * blockDim.x + threadIdx.x;
    int c = blockIdx.y, b = blockIdx.z;
    float carry = g_carry[(b * NCHUNK + c) * D_ + d];
    size_t base = ((size_t)b * L_ + (size_t)c * CLEN) * D_ + d;
    float A = 1.f;
    for (int t = 0; t < CLEN; t++) {
        size_t idx = base + (size_t)t * D_;
        A *= g_alpha[idx];
        g_h[idx] = fmaf(A, carry, g_h[idx]);
    }
}

// ---------------------------------------------------------------------------
// GEMM 3: ctx_out = ctx + silu(h @ Wc + bc), written straight to d_out region
// ---------------------------------------------------------------------------
__global__ __launch_bounds__(256) void gemm_ctx_kernel(
    const float* __restrict__ Wc, const float* __restrict__ bc,
    const float* __restrict__ ctx, float* __restrict__ out_ctx)
{
    __shared__ float As[16][128];
    __shared__ float Bs[16][128];
    const int n0 = blockIdx.x * 128;
    const int m0 = blockIdx.y * 128;
    const int tid = threadIdx.x;
    const int tx = tid & 15, ty = tid >> 4;

    float acc[8][8];
    #pragma unroll
    for (int i = 0; i < 8; i++)
        #pragma unroll
        for (int j = 0; j < 8; j++) acc[i][j] = 0.f;

    for (int k0 = 0; k0 < D_; k0 += 16) {
        #pragma unroll
        for (int i = 0; i < 2; i++) {
            int idx = tid + i * 256;
            int r = idx >> 2, c4 = idx & 3;
            float4 va = *(const float4*)(g_h + (size_t)(m0 + r) * D_ + k0 + c4 * 4);
            As[c4*4+0][r] = va.x; As[c4*4+1][r] = va.y;
            As[c4*4+2][r] = va.z; As[c4*4+3][r] = va.w;
        }
        #pragma unroll
        for (int i = 0; i < 2; i++) {
            int idx = tid + i * 256;
            int r = idx >> 5, c4 = idx & 31;
            *(float4*)&Bs[r][c4*4] = *(const float4*)(Wc + (size_t)(k0 + r) * D_ + n0 + c4 * 4);
        }
        __syncthreads();
        #pragma unroll
        for (int k = 0; k < 16; k++) {
            float ar[8], br[8];
            #pragma unroll
            for (int i = 0; i < 8; i++) ar[i] = As[k][ty * 8 + i];
            #pragma unroll
            for (int j = 0; j < 8; j++) br[j] = Bs[k][tx * 8 + j];
            #pragma unroll
            for (int i = 0; i < 8; i++)
                #pragma unroll
                for (int j = 0; j < 8; j++) acc[i][j] = fmaf(ar[i], br[j], acc[i][j]);
        }
        __syncthreads();
    }
    #pragma unroll
    for (int i = 0; i < 8; i++) {
        int m = m0 + ty * 8 + i;
        #pragma unroll
        for (int j = 0; j < 8; j++) {
            int n = n0 + tx * 8 + j;
            size_t idx = (size_t)m * D_ + n;
            out_ctx[idx] = ctx[idx] + siluf_(acc[i][j] + bc[n]);
        }
    }
}

// out_out = out + fetched
__global__ void out_add_kernel(const float* __restrict__ outin, float* __restrict__ dst) {
    int i = blockIdx.x * blockDim.x + threadIdx.x;   // float4 index
    float4 o = ((const float4*)outin)[i];
    float4 h = ((const float4*)g_h)[i];
    o.x += h.x; o.y += h.y; o.z += h.z; o.w += h.w;
    ((float4*)dst)[i] = o;
}

// ---------------------------------------------------------------------------
extern "C" void kernel_launch(void* const* d_in, const int* in_sizes, int n_in,
                              void* d_out, int out_size)
{
    const float* v    = (const float*)d_in[0];
    const float* ctx  = (const float*)d_in[1];
    const float* out  = (const float*)d_in[2];
    const float* alog = (const float*)d_in[3];
    const float* g    = (const float*)d_in[4];
    const float* Wa   = (const float*)d_in[5];
    const float* ba   = (const float*)d_in[6];
    const float* Wb   = (const float*)d_in[7];
    const float* bb   = (const float*)d_in[8];
    const float* Wc   = (const float*)d_in[9];
    const float* bc   = (const float*)d_in[10];

    float* o      = (float*)d_out;
    float* o_v    = o;
    float* o_ctx  = o + (size_t)TOT;
    float* o_out  = o + (size_t)2 * TOT;
    float* o_alog = o + (size_t)3 * TOT;

    // Pass-through outputs
    cudaMemcpyAsync(o_v,    v,    (size_t)TOT * sizeof(float), cudaMemcpyDeviceToDevice, 0);
    cudaMemcpyAsync(o_alog, alog, (size_t)TOT * sizeof(float), cudaMemcpyDeviceToDevice, 0);

    rms_kernel<<<M_, 256>>>(ctx, g);
    gemm_ab_kernel<<<dim3(16, 128), 256>>>(Wa, Wb, ba, bb);
    scan1_kernel<<<dim3(D_ / 256, NCHUNK, B_), 256>>>(v);
    scan2_kernel<<<B_, D_>>>();
    scan3_kernel<<<dim3(D_ / 256, NCHUNK, B_), 256>>>();
    gemm_ctx_kernel<<<dim3(8, 128), 256>>>(Wc, bc, ctx, o_ctx);
    out_add_kernel<<<TOT / 4 / 256, 256>>>(out, o_out);
}

// round 3
// speedup vs baseline: 2.6724x; 2.6724x over previous
#include <cuda_runtime.h>
#include <math.h>
#include <stdint.h>

#define B_ 4
#define L_ 4096
#define D_ 1024
#define M_ (B_*L_)            // 16384 rows
#define TOT (M_*D_)           // 16777216 elements per tensor
#define NCHUNK 32
#define CLEN (L_/NCHUNK)      // 128
#define KT (D_/16)            // 64 k-tiles

// ---- scratch (device globals: no runtime allocation allowed) ----
__device__ float g_norm [TOT];
__device__ float g_alpha[TOT];
__device__ float g_beta [TOT];
__device__ float g_h    [TOT];
__device__ float g_Aprod[B_*NCHUNK*D_];
__device__ float g_hend [B_*NCHUNK*D_];
__device__ float g_carry[B_*NCHUNK*D_];

__device__ __forceinline__ float sigmoidf_(float z) { return 1.f / (1.f + expf(-z)); }
__device__ __forceinline__ float siluf_(float z)    { return z   / (1.f + expf(-z)); }

__device__ __forceinline__ uint32_t f2tf(float x) {
    uint32_t r; asm("cvt.rna.tf32.f32 %0, %1;" : "=r"(r) : "f"(x)); return r;
}
__device__ __forceinline__ void mma_tf32(float c[4],
    uint32_t a0, uint32_t a1, uint32_t a2, uint32_t a3, uint32_t b0, uint32_t b1) {
    asm volatile(
        "mma.sync.aligned.m16n8k8.row.col.f32.tf32.tf32.f32 "
        "{%0,%1,%2,%3},{%4,%5,%6,%7},{%8,%9},{%0,%1,%2,%3};"
        : "+f"(c[0]), "+f"(c[1]), "+f"(c[2]), "+f"(c[3])
        : "r"(a0), "r"(a1), "r"(a2), "r"(a3), "r"(b0), "r"(b1));
}
__device__ __forceinline__ void cp16(void* dst, const void* src) {
    uint32_t d = (uint32_t)__cvta_generic_to_shared(dst);
    asm volatile("cp.async.cg.shared.global [%0], [%1], 16;" :: "r"(d), "l"(src));
}
#define CP_COMMIT()  asm volatile("cp.async.commit_group;")
#define CP_WAIT1()   asm volatile("cp.async.wait_group 1;")
#define CP_WAIT0()   asm volatile("cp.async.wait_group 0;")

#define AS_STRIDE 20    // 128 rows x (16 + 4 pad) floats: conflict-free frag reads
#define BS_STRIDE 136   // 16 rows x (128 + 8 pad) floats: conflict-free frag reads

// ---------------------------------------------------------------------------
// RMS norm: one block (256 thr) per row of 1024
// ---------------------------------------------------------------------------
__global__ void rms_kernel(const float* __restrict__ ctx, const float* __restrict__ g) {
    int row = blockIdx.x;
    const float* x = ctx + (size_t)row * D_;
    float s = 0.f;
    #pragma unroll
    for (int i = threadIdx.x; i < D_; i += 256) { float v = x[i]; s += v * v; }
    __shared__ float red[8];
    #pragma unroll
    for (int o = 16; o > 0; o >>= 1) s += __shfl_xor_sync(0xffffffffu, s, o);
    if ((threadIdx.x & 31) == 0) red[threadIdx.x >> 5] = s;
    __syncthreads();
    if (threadIdx.x < 8) {
        float t = red[threadIdx.x];
        #pragma unroll
        for (int o = 4; o > 0; o >>= 1) t += __shfl_xor_sync(0xffu, t, o);
        if (threadIdx.x == 0) red[0] = t;
    }
    __syncthreads();
    float inv = rsqrtf(red[0] * (1.f / D_) + 1e-6f);
    float* y = g_norm + (size_t)row * D_;
    for (int i = threadIdx.x; i < D_; i += 256) y[i] = x[i] * inv * g[i];
}

// ---------------------------------------------------------------------------
// tf32 tensor-core GEMM core: computes acc[4][4][4] for a 128x128 tile of
// A[M,1024] @ W[1024,N-slice]. Warp layout: 8 warps = 2(m) x 4(n);
// warp tile 64x32; mma m16n8k8.
// ---------------------------------------------------------------------------
struct TileCtx {
    int m0, ncol0, tid, lane, gid, tig, mw, nw;
};

__device__ __forceinline__ void gemm_tile_tf32(
    const float* __restrict__ aptr, const float* __restrict__ W,
    const TileCtx& c, float acc[4][4][4],
    float (*As)[128*AS_STRIDE], float (*Bs)[16*BS_STRIDE])
{
    const int tid = c.tid;

    auto loadA = [&](int stage, int k0) {
        #pragma unroll
        for (int i = 0; i < 2; i++) {
            int idx = tid + i * 256;
            int m = idx >> 2, kq = idx & 3;
            cp16(&As[stage][m * AS_STRIDE + kq * 4],
                 aptr + (size_t)(c.m0 + m) * D_ + k0 + kq * 4);
        }
    };
    auto loadB = [&](int stage, int k0) {
        #pragma unroll
        for (int i = 0; i < 2; i++) {
            int idx = tid + i * 256;
            int r = idx >> 5, cq = idx & 31;
            cp16(&Bs[stage][r * BS_STRIDE + cq * 4],
                 W + (size_t)(k0 + r) * D_ + c.ncol0 + cq * 4);
        }
    };

    loadA(0, 0); loadB(0, 0); CP_COMMIT();

    for (int kt = 0; kt < KT; kt++) {
        if (kt + 1 < KT) {
            int st = (kt + 1) & 1;
            loadA(st, (kt + 1) * 16); loadB(st, (kt + 1) * 16);
            CP_COMMIT();
            CP_WAIT1();
        } else {
            CP_WAIT0();
        }
        __syncthreads();

        const float* as = As[kt & 1];
        const float* bs = Bs[kt & 1];
        #pragma unroll
        for (int ks = 0; ks < 2; ks++) {
            const int kc = ks * 8;
            uint32_t af[4][4], bf[4][2];
            #pragma unroll
            for (int mt = 0; mt < 4; mt++) {
                int r = c.mw + mt * 16 + c.gid;
                af[mt][0] = f2tf(as[r * AS_STRIDE + kc + c.tig]);
                af[mt][1] = f2tf(as[(r + 8) * AS_STRIDE + kc + c.tig]);
                af[mt][2] = f2tf(as[r * AS_STRIDE + kc + c.tig + 4]);
                af[mt][3] = f2tf(as[(r + 8) * AS_STRIDE + kc + c.tig + 4]);
            }
            #pragma unroll
            for (int nt = 0; nt < 4; nt++) {
                int col = c.nw + nt * 8 + c.gid;
                bf[nt][0] = f2tf(bs[(kc + c.tig) * BS_STRIDE + col]);
                bf[nt][1] = f2tf(bs[(kc + c.tig + 4) * BS_STRIDE + col]);
            }
            #pragma unroll
            for (int mt = 0; mt < 4; mt++)
                #pragma unroll
                for (int nt = 0; nt < 4; nt++)
                    mma_tf32(acc[mt][nt], af[mt][0], af[mt][1], af[mt][2], af[mt][3],
                             bf[nt][0], bf[nt][1]);
        }
        __syncthreads();
    }
}

__device__ __forceinline__ TileCtx make_ctx(int m0, int ncol0) {
    TileCtx c;
    c.tid = threadIdx.x;
    c.lane = c.tid & 31;
    c.gid = c.lane >> 2;
    c.tig = c.lane & 3;
    int wid = c.tid >> 5;
    c.mw = (wid >> 2) * 64;
    c.nw = (wid & 3) * 32;
    c.m0 = m0; c.ncol0 = ncol0;
    return c;
}

// ---------------------------------------------------------------------------
// GEMM 1+2 fused: alpha = sigmoid(norm@Wa+ba), beta = silu(norm@Wb+bb)
// ---------------------------------------------------------------------------
__global__ __launch_bounds__(256) void gemm_ab_kernel(
    const float* __restrict__ Wa, const float* __restrict__ Wb,
    const float* __restrict__ ba, const float* __restrict__ bb)
{
    __shared__ __align__(16) float As[2][128*AS_STRIDE];
    __shared__ __align__(16) float Bs[2][16*BS_STRIDE];

    const int n0 = blockIdx.x * 128;
    const int m0 = blockIdx.y * 128;
    const bool isAlpha = (n0 < D_);
    const float* W    = isAlpha ? Wa : Wb;
    const float* bias = isAlpha ? ba : bb;
    const int ncol0   = isAlpha ? n0 : (n0 - D_);

    TileCtx c = make_ctx(m0, ncol0);
    float acc[4][4][4];
    #pragma unroll
    for (int i = 0; i < 4; i++)
        #pragma unroll
        for (int j = 0; j < 4; j++)
            #pragma unroll
            for (int k = 0; k < 4; k++) acc[i][j][k] = 0.f;

    gemm_tile_tf32(g_norm, W, c, acc, As, Bs);

    float* dst = isAlpha ? g_alpha : g_beta;
    #pragma unroll
    for (int mt = 0; mt < 4; mt++) {
        #pragma unroll
        for (int nt = 0; nt < 4; nt++) {
            int row0 = m0 + c.mw + mt * 16 + c.gid;
            int col  = ncol0 + c.nw + nt * 8 + 2 * c.tig;
            #pragma unroll
            for (int half = 0; half < 2; half++) {
                int row = row0 + half * 8;
                float z0 = acc[mt][nt][half*2+0] + bias[col];
                float z1 = acc[mt][nt][half*2+1] + bias[col+1];
                float2 o;
                if (isAlpha) { o.x = sigmoidf_(z0); o.y = sigmoidf_(z1); }
                else         { o.x = siluf_(z0);    o.y = siluf_(z1); }
                *(float2*)(dst + (size_t)row * D_ + col) = o;
            }
        }
    }
}

// ---------------------------------------------------------------------------
// GEMM 3: ctx_out = ctx + silu(h @ Wc + bc)
// ---------------------------------------------------------------------------
__global__ __launch_bounds__(256) void gemm_ctx_kernel(
    const float* __restrict__ Wc, const float* __restrict__ bc,
    const float* __restrict__ ctx, float* __restrict__ out_ctx)
{
    __shared__ __align__(16) float As[2][128*AS_STRIDE];
    __shared__ __align__(16) float Bs[2][16*BS_STRIDE];

    const int n0 = blockIdx.x * 128;
    const int m0 = blockIdx.y * 128;

    TileCtx c = make_ctx(m0, n0);
    float acc[4][4][4];
    #pragma unroll
    for (int i = 0; i < 4; i++)
        #pragma unroll
        for (int j = 0; j < 4; j++)
            #pragma unroll
            for (int k = 0; k < 4; k++) acc[i][j][k] = 0.f;

    gemm_tile_tf32(g_h, Wc, c, acc, As, Bs);

    #pragma unroll
    for (int mt = 0; mt < 4; mt++) {
        #pragma unroll
        for (int nt = 0; nt < 4; nt++) {
            int row0 = m0 + c.mw + mt * 16 + c.gid;
            int col  = n0 + c.nw + nt * 8 + 2 * c.tig;
            #pragma unroll
            for (int half = 0; half < 2; half++) {
                int row = row0 + half * 8;
                size_t idx = (size_t)row * D_ + col;
                float z0 = acc[mt][nt][half*2+0] + bc[col];
                float z1 = acc[mt][nt][half*2+1] + bc[col+1];
                float2 cc = *(const float2*)(ctx + idx);
                float2 o;
                o.x = cc.x + siluf_(z0);
                o.y = cc.y + siluf_(z1);
                *(float2*)(out_ctx + idx) = o;
            }
        }
    }
}

// ---------------------------------------------------------------------------
// Chunked scan (3 passes). h_t = a_t*h_{t-1} + x_t, x = v*beta*sqrt(clip(1-a^2))
// ---------------------------------------------------------------------------
__global__ void scan1_kernel(const float* __restrict__ v) {
    int d = blockIdx.x * blockDim.x + threadIdx.x;
    int cch = blockIdx.y, b = blockIdx.z;
    size_t base = ((size_t)b * L_ + (size_t)cch * CLEN) * D_ + d;
    float h = 0.f, A = 1.f;
    for (int t = 0; t < CLEN; t++) {
        size_t idx = base + (size_t)t * D_;
        float a  = g_alpha[idx];
        float ws = sqrtf(fmaxf(1.f - a * a, 1e-6f));
        float x  = v[idx] * g_beta[idx] * ws;
        h = fmaf(a, h, x);
        A *= a;
        g_h[idx] = h;
    }
    int sidx = (b * NCHUNK + cch) * D_ + d;
    g_hend[sidx] = h; g_Aprod[sidx] = A;
}

// 256 threads/block (reg cap 255/thread), grid (D/256, B)
__global__ __launch_bounds__(256) void scan2_kernel() {
    int d = blockIdx.x * 256 + threadIdx.x;
    int b = blockIdx.y;
    float Ap[NCHUNK], He[NCHUNK];
    #pragma unroll
    for (int cc = 0; cc < NCHUNK; cc++) {          // batched loads: no dep chain
        int sidx = (b * NCHUNK + cc) * D_ + d;
        Ap[cc] = g_Aprod[sidx];
        He[cc] = g_hend[sidx];
    }
    float carry = 0.f;
    #pragma unroll
    for (int cc = 0; cc < NCHUNK; cc++) {
        g_carry[(b * NCHUNK + cc) * D_ + d] = carry;
        carry = fmaf(Ap[cc], carry, He[cc]);
    }
}

__global__ void scan3_kernel() {
    if (blockIdx.y == 0) return;   // chunk 0: carry is zero
    int d = blockIdx.x * blockDim.x + threadIdx.x;
    int cch = blockIdx.y, b = blockIdx.z;
    float carry = g_carry[(b * NCHUNK + cch) * D_ + d];
    size_t base = ((size_t)b * L_ + (size_t)cch * CLEN) * D_ + d;
    float A = 1.f;
    for (int t = 0; t < CLEN; t++) {
        size_t idx = base + (size_t)t * D_;
        A *= g_alpha[idx];
        g_h[idx] = fmaf(A, carry, g_h[idx]);
    }
}

// out_out = out + fetched
__global__ void out_add_kernel(const float* __restrict__ outin, float* __restrict__ dst) {
    int i = blockIdx.x * blockDim.x + threadIdx.x;   // float4 index
    float4 o = ((const float4*)outin)[i];
    float4 h = ((const float4*)g_h)[i];
    o.x += h.x; o.y += h.y; o.z += h.z; o.w += h.w;
    ((float4*)dst)[i] = o;
}

// ---------------------------------------------------------------------------
extern "C" void kernel_launch(void* const* d_in, const int* in_sizes, int n_in,
                              void* d_out, int out_size)
{
    const float* v    = (const float*)d_in[0];
    const float* ctx  = (const float*)d_in[1];
    const float* out  = (const float*)d_in[2];
    const float* alog = (const float*)d_in[3];
    const float* g    = (const float*)d_in[4];
    const float* Wa   = (const float*)d_in[5];
    const float* ba   = (const float*)d_in[6];
    const float* Wb   = (const float*)d_in[7];
    const float* bb   = (const float*)d_in[8];
    const float* Wc   = (const float*)d_in[9];
    const float* bc   = (const float*)d_in[10];

    float* o      = (float*)d_out;
    float* o_v    = o;
    float* o_ctx  = o + (size_t)TOT;
    float* o_out  = o + (size_t)2 * TOT;
    float* o_alog = o + (size_t)3 * TOT;

    // Pass-through outputs
    cudaMemcpyAsync(o_v,    v,    (size_t)TOT * sizeof(float), cudaMemcpyDeviceToDevice, 0);
    cudaMemcpyAsync(o_alog, alog, (size_t)TOT * sizeof(float), cudaMemcpyDeviceToDevice, 0);

    rms_kernel<<<M_, 256>>>(ctx, g);
    gemm_ab_kernel<<<dim3(16, 128), 256>>>(Wa, Wb, ba, bb);
    scan1_kernel<<<dim3(D_ / 256, NCHUNK, B_), 256>>>(v);
    scan2_kernel<<<dim3(D_ / 256, B_), 256>>>();
    scan3_kernel<<<dim3(D_ / 256, NCHUNK, B_), 256>>>();
    gemm_ctx_kernel<<<dim3(8, 128), 256>>>(Wc, bc, ctx, o_ctx);
    out_add_kernel<<<TOT / 4 / 256, 256>>>(out, o_out);
}

// round 5
// speedup vs baseline: 3.7796x; 1.4143x over previous
#include <cuda_runtime.h>
#include <math.h>
#include <stdint.h>

#define B_ 4
#define L_ 4096
#define D_ 1024
#define M_ (B_*L_)            // 16384 rows
#define TOT (M_*D_)           // 16777216 elements per tensor
#define NCHUNK 32
#define CLEN (L_/NCHUNK)      // 128
#define KT (D_/16)            // 64 k-tiles of 16

// ---- GEMM tiling: block 128(M) x 256(N), 8 warps in 2x4, warp tile 64x64 ----
#define AS_ST 20               // 16 k + 4 pad
#define BS_ST 264              // 256 n + 8 pad
#define A_STAGE (128*AS_ST)    // 2560 floats
#define B_STAGE (16*BS_ST)     // 4224 floats
#define SMEM_FLOATS (2*A_STAGE + 2*B_STAGE)     // 13568
#define SMEM_BYTES  (SMEM_FLOATS*4)             // 54272

// ---- scratch (device globals: no runtime allocation allowed) ----
__device__ float g_norm [TOT];
__device__ float g_alpha[TOT];
__device__ float g_beta [TOT];
__device__ float g_h    [TOT];
__device__ float g_Aprod[B_*NCHUNK*D_];
__device__ float g_hend [B_*NCHUNK*D_];
__device__ float g_carry[B_*NCHUNK*D_];

__device__ __forceinline__ float sigmoidf_(float z) { return 1.f / (1.f + expf(-z)); }
__device__ __forceinline__ float siluf_(float z)    { return z   / (1.f + expf(-z)); }

__device__ __forceinline__ void mma_tf32(float c[4],
    uint32_t a0, uint32_t a1, uint32_t a2, uint32_t a3, uint32_t b0, uint32_t b1) {
    asm volatile(
        "mma.sync.aligned.m16n8k8.row.col.f32.tf32.tf32.f32 "
        "{%0,%1,%2,%3},{%4,%5,%6,%7},{%8,%9},{%0,%1,%2,%3};"
        : "+f"(c[0]), "+f"(c[1]), "+f"(c[2]), "+f"(c[3])
        : "r"(a0), "r"(a1), "r"(a2), "r"(a3), "r"(b0), "r"(b1));
}
__device__ __forceinline__ void cp16(void* dst, const void* src) {
    uint32_t d = (uint32_t)__cvta_generic_to_shared(dst);
    asm volatile("cp.async.cg.shared.global [%0], [%1], 16;" :: "r"(d), "l"(src));
}
#define CP_COMMIT()  asm volatile("cp.async.commit_group;")
#define CP_WAIT1()   asm volatile("cp.async.wait_group 1;")
#define CP_WAIT0()   asm volatile("cp.async.wait_group 0;")

// ---------------------------------------------------------------------------
// RMS norm
// ---------------------------------------------------------------------------
__global__ void rms_kernel(const float* __restrict__ ctx, const float* __restrict__ g) {
    int row = blockIdx.x;
    const float* x = ctx + (size_t)row * D_;
    float s = 0.f;
    #pragma unroll
    for (int i = threadIdx.x; i < D_; i += 256) { float v = x[i]; s += v * v; }
    __shared__ float red[8];
    #pragma unroll
    for (int o = 16; o > 0; o >>= 1) s += __shfl_xor_sync(0xffffffffu, s, o);
    if ((threadIdx.x & 31) == 0) red[threadIdx.x >> 5] = s;
    __syncthreads();
    if (threadIdx.x < 8) {
        float t = red[threadIdx.x];
        #pragma unroll
        for (int o = 4; o > 0; o >>= 1) t += __shfl_xor_sync(0xffu, t, o);
        if (threadIdx.x == 0) red[0] = t;
    }
    __syncthreads();
    float inv = rsqrtf(red[0] * (1.f / D_) + 1e-6f);
    float* y = g_norm + (size_t)row * D_;
    for (int i = threadIdx.x; i < D_; i += 256) y[i] = x[i] * inv * g[i];
}

// ---------------------------------------------------------------------------
// Big-tile tf32 mainloop: acc[4][8][4] for 128x256 tile of A @ W(+ncol0 slice).
// A row-major [M,1024]; W row-major [1024,1024]. Raw fp32 bits into tf32 mma.
// ---------------------------------------------------------------------------
__device__ __forceinline__ void gemm_core(
    float* sm, const float* __restrict__ Aptr, const float* __restrict__ W,
    int m0, int ncol0, float acc[4][8][4])
{
    const int tid = threadIdx.x;
    float* As = sm;                 // [2][A_STAGE]
    float* Bs = sm + 2 * A_STAGE;   // [2][B_STAGE]

    auto loadA = [&](int stage, int k0) {
        #pragma unroll
        for (int i = 0; i < 2; i++) {
            int idx = tid + i * 256;           // 0..511
            int r = idx >> 2, q = idx & 3;
            cp16(As + stage * A_STAGE + r * AS_ST + q * 4,
                 Aptr + (size_t)(m0 + r) * D_ + k0 + q * 4);
        }
    };
    auto loadB = [&](int stage, int k0) {
        #pragma unroll
        for (int i = 0; i < 4; i++) {
            int idx = tid + i * 256;           // 0..1023
            int r = idx >> 6, c = idx & 63;
            cp16(Bs + stage * B_STAGE + r * BS_ST + c * 4,
                 W + (size_t)(k0 + r) * D_ + ncol0 + c * 4);
        }
    };

    const int lane = tid & 31;
    const int gid = lane >> 2, tig = lane & 3;
    const int wid = tid >> 5;
    const int wm = (wid >> 2) * 64;       // 0 / 64
    const int wn = (wid & 3) * 64;        // 0..192

    loadA(0, 0); loadB(0, 0); CP_COMMIT();

    for (int kt = 0; kt < KT; kt++) {
        if (kt + 1 < KT) {
            int st = (kt + 1) & 1;
            loadA(st, (kt + 1) * 16); loadB(st, (kt + 1) * 16);
            CP_COMMIT();
            CP_WAIT1();
        } else {
            CP_WAIT0();
        }
        __syncthreads();

        const float* as = As + (kt & 1) * A_STAGE;
        const float* bs = Bs + (kt & 1) * B_STAGE;
        #pragma unroll
        for (int ks = 0; ks < 2; ks++) {
            const int kc = ks * 8;
            uint32_t af[4][4], bf[8][2];
            #pragma unroll
            for (int mt = 0; mt < 4; mt++) {
                int r = wm + mt * 16 + gid;
                af[mt][0] = __float_as_uint(as[r * AS_ST + kc + tig]);
                af[mt][1] = __float_as_uint(as[(r + 8) * AS_ST + kc + tig]);
                af[mt][2] = __float_as_uint(as[r * AS_ST + kc + tig + 4]);
                af[mt][3] = __float_as_uint(as[(r + 8) * AS_ST + kc + tig + 4]);
            }
            #pragma unroll
            for (int nt = 0; nt < 8; nt++) {
                int col = wn + nt * 8 + gid;
                bf[nt][0] = __float_as_uint(bs[(kc + tig) * BS_ST + col]);
                bf[nt][1] = __float_as_uint(bs[(kc + tig + 4) * BS_ST + col]);
            }
            #pragma unroll
            for (int mt = 0; mt < 4; mt++)
                #pragma unroll
                for (int nt = 0; nt < 8; nt++)
                    mma_tf32(acc[mt][nt], af[mt][0], af[mt][1], af[mt][2], af[mt][3],
                             bf[nt][0], bf[nt][1]);
        }
        __syncthreads();
    }
}

// ---------------------------------------------------------------------------
// GEMM 1+2 fused: alpha = sigmoid(norm@Wa+ba), beta = silu(norm@Wb+bb)
// grid (8, 128): x<4 -> alpha cols [0,1024), x>=4 -> beta
// ---------------------------------------------------------------------------
__global__ __launch_bounds__(256, 1) void gemm_ab_kernel(
    const float* __restrict__ Wa, const float* __restrict__ Wb,
    const float* __restrict__ ba, const float* __restrict__ bb)
{
    extern __shared__ float sm[];
    const int m0 = blockIdx.y * 128;
    const bool isA = (blockIdx.x < 4);
    const int ncol0 = (isA ? blockIdx.x : blockIdx.x - 4) * 256;
    const float* W    = isA ? Wa : Wb;
    const float* bias = isA ? ba : bb;
    float* dst        = isA ? g_alpha : g_beta;

    float acc[4][8][4];
    #pragma unroll
    for (int i = 0; i < 4; i++)
        #pragma unroll
        for (int j = 0; j < 8; j++)
            #pragma unroll
            for (int k = 0; k < 4; k++) acc[i][j][k] = 0.f;

    gemm_core(sm, g_norm, W, m0, ncol0, acc);

    const int lane = threadIdx.x & 31;
    const int gid = lane >> 2, tig = lane & 3;
    const int wid = threadIdx.x >> 5;
    const int wm = (wid >> 2) * 64, wn = (wid & 3) * 64;
    #pragma unroll
    for (int mt = 0; mt < 4; mt++) {
        #pragma unroll
        for (int nt = 0; nt < 8; nt++) {
            int col = ncol0 + wn + nt * 8 + 2 * tig;
            #pragma unroll
            for (int half = 0; half < 2; half++) {
                int row = m0 + wm + mt * 16 + gid + half * 8;
                float z0 = acc[mt][nt][half*2+0] + bias[col];
                float z1 = acc[mt][nt][half*2+1] + bias[col+1];
                float2 o;
                if (isA) { o.x = sigmoidf_(z0); o.y = sigmoidf_(z1); }
                else     { o.x = siluf_(z0);    o.y = siluf_(z1); }
                *(float2*)(dst + (size_t)row * D_ + col) = o;
            }
        }
    }
}

// ---------------------------------------------------------------------------
// GEMM 3: ctx_out = ctx + silu(h @ Wc + bc). grid (4, 128)
// ---------------------------------------------------------------------------
__global__ __launch_bounds__(256, 1) void gemm_ctx_kernel(
    const float* __restrict__ Wc, const float* __restrict__ bc,
    const float* __restrict__ ctx, float* __restrict__ out_ctx)
{
    extern __shared__ float sm[];
    const int m0 = blockIdx.y * 128;
    const int ncol0 = blockIdx.x * 256;

    float acc[4][8][4];
    #pragma unroll
    for (int i = 0; i < 4; i++)
        #pragma unroll
        for (int j = 0; j < 8; j++)
            #pragma unroll
            for (int k = 0; k < 4; k++) acc[i][j][k] = 0.f;

    gemm_core(sm, g_h, Wc, m0, ncol0, acc);

    const int lane = threadIdx.x & 31;
    const int gid = lane >> 2, tig = lane & 3;
    const int wid = threadIdx.x >> 5;
    const int wm = (wid >> 2) * 64, wn = (wid & 3) * 64;
    #pragma unroll
    for (int mt = 0; mt < 4; mt++) {
        #pragma unroll
        for (int nt = 0; nt < 8; nt++) {
            int col = ncol0 + wn + nt * 8 + 2 * tig;
            #pragma unroll
            for (int half = 0; half < 2; half++) {
                int row = m0 + wm + mt * 16 + gid + half * 8;
                size_t idx = (size_t)row * D_ + col;
                float2 cc = *(const float2*)(ctx + idx);
                float2 o;
                o.x = cc.x + siluf_(acc[mt][nt][half*2+0] + bc[col]);
                o.y = cc.y + siluf_(acc[mt][nt][half*2+1] + bc[col+1]);
                *(float2*)(out_ctx + idx) = o;
            }
        }
    }
}

// ---------------------------------------------------------------------------
// Chunked scan. Pass 1 also emits the v passthrough copy.
// ---------------------------------------------------------------------------
__global__ void scan1_kernel(const float* __restrict__ v, float* __restrict__ o_v) {
    int d = blockIdx.x * blockDim.x + threadIdx.x;
    int cch = blockIdx.y, b = blockIdx.z;
    size_t base = ((size_t)b * L_ + (size_t)cch * CLEN) * D_ + d;
    float h = 0.f, A = 1.f;
    for (int t = 0; t < CLEN; t++) {
        size_t idx = base + (size_t)t * D_;
        float a  = g_alpha[idx];
        float vv = v[idx];
        float ws = sqrtf(fmaxf(1.f - a * a, 1e-6f));
        float x  = vv * g_beta[idx] * ws;
        h = fmaf(a, h, x);
        A *= a;
        g_h[idx] = h;
        o_v[idx] = vv;
    }
    int sidx = (b * NCHUNK + cch) * D_ + d;
    g_hend[sidx] = h; g_Aprod[sidx] = A;
}

__global__ __launch_bounds__(256) void scan2_kernel() {
    int d = blockIdx.x * 256 + threadIdx.x;
    int b = blockIdx.y;
    float Ap[NCHUNK], He[NCHUNK];
    #pragma unroll
    for (int cc = 0; cc < NCHUNK; cc++) {
        int sidx = (b * NCHUNK + cc) * D_ + d;
        Ap[cc] = g_Aprod[sidx];
        He[cc] = g_hend[sidx];
    }
    float carry = 0.f;
    #pragma unroll
    for (int cc = 0; cc < NCHUNK; cc++) {
        g_carry[(b * NCHUNK + cc) * D_ + d] = carry;
        carry = fmaf(Ap[cc], carry, He[cc]);
    }
}

// Pass 3 fused with out_out = out + fetched
__global__ void scan3_out_kernel(const float* __restrict__ out_in,
                                 float* __restrict__ o_out) {
    int d = blockIdx.x * blockDim.x + threadIdx.x;
    int cch = blockIdx.y, b = blockIdx.z;
    size_t base = ((size_t)b * L_ + (size_t)cch * CLEN) * D_ + d;
    if (cch == 0) {
        for (int t = 0; t < CLEN; t++) {
            size_t idx = base + (size_t)t * D_;
            o_out[idx] = out_in[idx] + g_h[idx];
        }
        return;
    }
    float carry = g_carry[(b * NCHUNK + cch) * D_ + d];
    float A = 1.f;
    for (int t = 0; t < CLEN; t++) {
        size_t idx = base + (size_t)t * D_;
        A *= g_alpha[idx];
        float h = fmaf(A, carry, g_h[idx]);
        g_h[idx] = h;
        o_out[idx] = out_in[idx] + h;
    }
}

// ---------------------------------------------------------------------------
extern "C" void kernel_launch(void* const* d_in, const int* in_sizes, int n_in,
                              void* d_out, int out_size)
{
    const float* v    = (const float*)d_in[0];
    const float* ctx  = (const float*)d_in[1];
    const float* out  = (const float*)d_in[2];
    const float* alog = (const float*)d_in[3];
    const float* g    = (const float*)d_in[4];
    const float* Wa   = (const float*)d_in[5];
    const float* ba   = (const float*)d_in[6];
    const float* Wb   = (const float*)d_in[7];
    const float* bb   = (const float*)d_in[8];
    const float* Wc   = (const float*)d_in[9];
    const float* bc   = (const float*)d_in[10];

    float* o      = (float*)d_out;
    float* o_v    = o;
    float* o_ctx  = o + (size_t)TOT;
    float* o_out  = o + (size_t)2 * TOT;
    float* o_alog = o + (size_t)3 * TOT;

    static int smem_set = 0;
    if (!smem_set) {
        cudaFuncSetAttribute(gemm_ab_kernel,  cudaFuncAttributeMaxDynamicSharedMemorySize, SMEM_BYTES);
        cudaFuncSetAttribute(gemm_ctx_kernel, cudaFuncAttributeMaxDynamicSharedMemorySize, SMEM_BYTES);
        smem_set = 1;
    }

    cudaMemcpyAsync(o_alog, alog, (size_t)TOT * sizeof(float), cudaMemcpyDeviceToDevice, 0);

    rms_kernel<<<M_, 256>>>(ctx, g);
    gemm_ab_kernel<<<dim3(8, 128), 256, SMEM_BYTES>>>(Wa, Wb, ba, bb);
    scan1_kernel<<<dim3(D_ / 256, NCHUNK, B_), 256>>>(v, o_v);
    scan2_kernel<<<dim3(D_ / 256, B_), 256>>>();
    scan3_out_kernel<<<dim3(D_ / 256, NCHUNK, B_), 256>>>(out, o_out);
    gemm_ctx_kernel<<<dim3(4, 128), 256, SMEM_BYTES>>>(Wc, bc, ctx, o_ctx);
}

// round 6
// speedup vs baseline: 3.8026x; 1.0061x over previous
#include <cuda_runtime.h>
#include <math.h>
#include <stdint.h>

#define B_ 4
#define L_ 4096
#define D_ 1024
#define M_ (B_*L_)            // 16384 rows
#define TOT (M_*D_)           // 16777216 elements per tensor
#define NCHUNK 32
#define CLEN (L_/NCHUNK)      // 128
#define KT (D_/16)            // 64 k-tiles of 16

// ---- GEMM tiling: block 128(M) x 256(N), 8 warps in 2x4, warp tile 64x64 ----
#define STAGES 5
#define AS_ST 20               // 16 k + 4 pad
#define BS_ST 264              // 256 n + 8 pad
#define A_STAGE (128*AS_ST)    // 2560 floats
#define B_STAGE (16*BS_ST)     // 4224 floats
#define STAGE_FLOATS (A_STAGE + B_STAGE)            // 6784
#define SMEM_FLOATS (STAGES*STAGE_FLOATS)           // 33920
#define SMEM_BYTES  (SMEM_FLOATS*4)                 // 135680

// ---- scratch (device globals: no runtime allocation allowed) ----
__device__ float g_norm [TOT];
__device__ float g_alpha[TOT];
__device__ float g_beta [TOT];
__device__ float g_h    [TOT];
__device__ float g_Aprod[B_*NCHUNK*D_];
__device__ float g_hend [B_*NCHUNK*D_];
__device__ float g_carry[B_*NCHUNK*D_];

__device__ __forceinline__ float sigmoidf_(float z) { return 1.f / (1.f + expf(-z)); }
__device__ __forceinline__ float siluf_(float z)    { return z   / (1.f + expf(-z)); }

__device__ __forceinline__ void mma_tf32(float c[4],
    uint32_t a0, uint32_t a1, uint32_t a2, uint32_t a3, uint32_t b0, uint32_t b1) {
    asm volatile(
        "mma.sync.aligned.m16n8k8.row.col.f32.tf32.tf32.f32 "
        "{%0,%1,%2,%3},{%4,%5,%6,%7},{%8,%9},{%0,%1,%2,%3};"
        : "+f"(c[0]), "+f"(c[1]), "+f"(c[2]), "+f"(c[3])
        : "r"(a0), "r"(a1), "r"(a2), "r"(a3), "r"(b0), "r"(b1));
}
__device__ __forceinline__ void cp16(void* dst, const void* src) {
    uint32_t d = (uint32_t)__cvta_generic_to_shared(dst);
    asm volatile("cp.async.cg.shared.global [%0], [%1], 16;" :: "r"(d), "l"(src));
}
#define CP_COMMIT()  asm volatile("cp.async.commit_group;")
#define CP_WAIT3()   asm volatile("cp.async.wait_group 3;")

// ---------------------------------------------------------------------------
// RMS norm
// ---------------------------------------------------------------------------
__global__ void rms_kernel(const float* __restrict__ ctx, const float* __restrict__ g) {
    int row = blockIdx.x;
    const float* x = ctx + (size_t)row * D_;
    float s = 0.f;
    #pragma unroll
    for (int i = threadIdx.x; i < D_; i += 256) { float v = x[i]; s += v * v; }
    __shared__ float red[8];
    #pragma unroll
    for (int o = 16; o > 0; o >>= 1) s += __shfl_xor_sync(0xffffffffu, s, o);
    if ((threadIdx.x & 31) == 0) red[threadIdx.x >> 5] = s;
    __syncthreads();
    if (threadIdx.x < 8) {
        float t = red[threadIdx.x];
        #pragma unroll
        for (int o = 4; o > 0; o >>= 1) t += __shfl_xor_sync(0xffu, t, o);
        if (threadIdx.x == 0) red[0] = t;
    }
    __syncthreads();
    float inv = rsqrtf(red[0] * (1.f / D_) + 1e-6f);
    float* y = g_norm + (size_t)row * D_;
    for (int i = threadIdx.x; i < D_; i += 256) y[i] = x[i] * inv * g[i];
}

// ---------------------------------------------------------------------------
// Big-tile tf32 mainloop, 5-stage cp.async pipeline.
// acc[4][8][4] for 128x256 tile of A @ W(+ncol0). Raw fp32 bits into tf32 mma.
// ---------------------------------------------------------------------------
__device__ __forceinline__ void gemm_core(
    float* sm, const float* __restrict__ Aptr, const float* __restrict__ W,
    int m0, int ncol0, float acc[4][8][4])
{
    const int tid = threadIdx.x;

    auto ld_stage = [&](int stage, int kt) {
        const int k0 = kt * 16;
        float* As = sm + stage * STAGE_FLOATS;
        float* Bs = As + A_STAGE;
        #pragma unroll
        for (int i = 0; i < 2; i++) {
            int idx = tid + i * 256;           // 0..511
            int r = idx >> 2, q = idx & 3;
            cp16(As + r * AS_ST + q * 4,
                 Aptr + (size_t)(m0 + r) * D_ + k0 + q * 4);
        }
        #pragma unroll
        for (int i = 0; i < 4; i++) {
            int idx = tid + i * 256;           // 0..1023
            int r = idx >> 6, c = idx & 63;
            cp16(Bs + r * BS_ST + c * 4,
                 W + (size_t)(k0 + r) * D_ + ncol0 + c * 4);
        }
    };

    const int lane = tid & 31;
    const int gid = lane >> 2, tig = lane & 3;
    const int wid = tid >> 5;
    const int wm = (wid >> 2) * 64;       // 0 / 64
    const int wn = (wid & 3) * 64;        // 0..192

    #pragma unroll
    for (int s = 0; s < STAGES - 1; s++) { ld_stage(s, s); CP_COMMIT(); }

    int s_cur = 0, s_ld = STAGES - 1;
    for (int kt = 0; kt < KT; kt++) {
        CP_WAIT3();
        __syncthreads();

        const float* as = sm + s_cur * STAGE_FLOATS;
        const float* bs = as + A_STAGE;
        #pragma unroll
        for (int ks = 0; ks < 2; ks++) {
            const int kc = ks * 8;
            uint32_t af[4][4], bf[8][2];
            #pragma unroll
            for (int mt = 0; mt < 4; mt++) {
                int r = wm + mt * 16 + gid;
                af[mt][0] = __float_as_uint(as[r * AS_ST + kc + tig]);
                af[mt][1] = __float_as_uint(as[(r + 8) * AS_ST + kc + tig]);
                af[mt][2] = __float_as_uint(as[r * AS_ST + kc + tig + 4]);
                af[mt][3] = __float_as_uint(as[(r + 8) * AS_ST + kc + tig + 4]);
            }
            #pragma unroll
            for (int nt = 0; nt < 8; nt++) {
                int col = wn + nt * 8 + gid;
                bf[nt][0] = __float_as_uint(bs[(kc + tig) * BS_ST + col]);
                bf[nt][1] = __float_as_uint(bs[(kc + tig + 4) * BS_ST + col]);
            }
            #pragma unroll
            for (int mt = 0; mt < 4; mt++)
                #pragma unroll
                for (int nt = 0; nt < 8; nt++)
                    mma_tf32(acc[mt][nt], af[mt][0], af[mt][1], af[mt][2], af[mt][3],
                             bf[nt][0], bf[nt][1]);
        }
        __syncthreads();     // all warps done reading s_ld's target before overwrite

        int nk = kt + STAGES - 1;
        if (nk < KT) ld_stage(s_ld, nk);
        CP_COMMIT();
        if (++s_cur == STAGES) s_cur = 0;
        if (++s_ld == STAGES) s_ld = 0;
    }
}

// ---------------------------------------------------------------------------
// GEMM 1+2 fused: alpha = sigmoid(norm@Wa+ba), beta = silu(norm@Wb+bb)
// grid (8, 128): x<4 -> alpha cols, x>=4 -> beta
// ---------------------------------------------------------------------------
__global__ __launch_bounds__(256, 1) void gemm_ab_kernel(
    const float* __restrict__ Wa, const float* __restrict__ Wb,
    const float* __restrict__ ba, const float* __restrict__ bb)
{
    extern __shared__ float sm[];
    const int m0 = blockIdx.y * 128;
    const bool isA = (blockIdx.x < 4);
    const int ncol0 = (isA ? blockIdx.x : blockIdx.x - 4) * 256;
    const float* W    = isA ? Wa : Wb;
    const float* bias = isA ? ba : bb;
    float* dst        = isA ? g_alpha : g_beta;

    float acc[4][8][4];
    #pragma unroll
    for (int i = 0; i < 4; i++)
        #pragma unroll
        for (int j = 0; j < 8; j++)
            #pragma unroll
            for (int k = 0; k < 4; k++) acc[i][j][k] = 0.f;

    gemm_core(sm, g_norm, W, m0, ncol0, acc);

    const int lane = threadIdx.x & 31;
    const int gid = lane >> 2, tig = lane & 3;
    const int wid = threadIdx.x >> 5;
    const int wm = (wid >> 2) * 64, wn = (wid & 3) * 64;
    #pragma unroll
    for (int mt = 0; mt < 4; mt++) {
        #pragma unroll
        for (int nt = 0; nt < 8; nt++) {
            int col = ncol0 + wn + nt * 8 + 2 * tig;
            #pragma unroll
            for (int half = 0; half < 2; half++) {
                int row = m0 + wm + mt * 16 + gid + half * 8;
                float z0 = acc[mt][nt][half*2+0] + bias[col];
                float z1 = acc[mt][nt][half*2+1] + bias[col+1];
                float2 o;
                if (isA) { o.x = sigmoidf_(z0); o.y = sigmoidf_(z1); }
                else     { o.x = siluf_(z0);    o.y = siluf_(z1); }
                *(float2*)(dst + (size_t)row * D_ + col) = o;
            }
        }
    }
}

// ---------------------------------------------------------------------------
// GEMM 3: ctx_out = ctx + silu(h @ Wc + bc). grid (4, 128)
// ---------------------------------------------------------------------------
__global__ __launch_bounds__(256, 1) void gemm_ctx_kernel(
    const float* __restrict__ Wc, const float* __restrict__ bc,
    const float* __restrict__ ctx, float* __restrict__ out_ctx)
{
    extern __shared__ float sm[];
    const int m0 = blockIdx.y * 128;
    const int ncol0 = blockIdx.x * 256;

    float acc[4][8][4];
    #pragma unroll
    for (int i = 0; i < 4; i++)
        #pragma unroll
        for (int j = 0; j < 8; j++)
            #pragma unroll
            for (int k = 0; k < 4; k++) acc[i][j][k] = 0.f;

    gemm_core(sm, g_h, Wc, m0, ncol0, acc);

    const int lane = threadIdx.x & 31;
    const int gid = lane >> 2, tig = lane & 3;
    const int wid = threadIdx.x >> 5;
    const int wm = (wid >> 2) * 64, wn = (wid & 3) * 64;
    #pragma unroll
    for (int mt = 0; mt < 4; mt++) {
        #pragma unroll
        for (int nt = 0; nt < 8; nt++) {
            int col = ncol0 + wn + nt * 8 + 2 * tig;
            #pragma unroll
            for (int half = 0; half < 2; half++) {
                int row = m0 + wm + mt * 16 + gid + half * 8;
                size_t idx = (size_t)row * D_ + col;
                float2 cc = *(const float2*)(ctx + idx);
                float2 o;
                o.x = cc.x + siluf_(acc[mt][nt][half*2+0] + bc[col]);
                o.y = cc.y + siluf_(acc[mt][nt][half*2+1] + bc[col+1]);
                *(float2*)(out_ctx + idx) = o;
            }
        }
    }
}

// ---------------------------------------------------------------------------
// Chunked scan. Pass 1 also emits the v passthrough copy.
// ---------------------------------------------------------------------------
__global__ void scan1_kernel(const float* __restrict__ v, float* __restrict__ o_v) {
    int d = blockIdx.x * blockDim.x + threadIdx.x;
    int cch = blockIdx.y, b = blockIdx.z;
    size_t base = ((size_t)b * L_ + (size_t)cch * CLEN) * D_ + d;
    float h = 0.f, A = 1.f;
    for (int t = 0; t < CLEN; t++) {
        size_t idx = base + (size_t)t * D_;
        float a  = g_alpha[idx];
        float vv = v[idx];
        float ws = sqrtf(fmaxf(1.f - a * a, 1e-6f));
        float x  = vv * g_beta[idx] * ws;
        h = fmaf(a, h, x);
        A *= a;
        g_h[idx] = h;
        o_v[idx] = vv;
    }
    int sidx = (b * NCHUNK + cch) * D_ + d;
    g_hend[sidx] = h; g_Aprod[sidx] = A;
}

__global__ __launch_bounds__(256) void scan2_kernel() {
    int d = blockIdx.x * 256 + threadIdx.x;
    int b = blockIdx.y;
    float Ap[NCHUNK], He[NCHUNK];
    #pragma unroll
    for (int cc = 0; cc < NCHUNK; cc++) {
        int sidx = (b * NCHUNK + cc) * D_ + d;
        Ap[cc] = g_Aprod[sidx];
        He[cc] = g_hend[sidx];
    }
    float carry = 0.f;
    #pragma unroll
    for (int cc = 0; cc < NCHUNK; cc++) {
        g_carry[(b * NCHUNK + cc) * D_ + d] = carry;
        carry = fmaf(Ap[cc], carry, He[cc]);
    }
}

// Pass 3 fused with out_out = out + fetched
__global__ void scan3_out_kernel(const float* __restrict__ out_in,
                                 float* __restrict__ o_out) {
    int d = blockIdx.x * blockDim.x + threadIdx.x;
    int cch = blockIdx.y, b = blockIdx.z;
    size_t base = ((size_t)b * L_ + (size_t)cch * CLEN) * D_ + d;
    if (cch == 0) {
        for (int t = 0; t < CLEN; t++) {
            size_t idx = base + (size_t)t * D_;
            o_out[idx] = out_in[idx] + g_h[idx];
        }
        return;
    }
    float carry = g_carry[(b * NCHUNK + cch) * D_ + d];
    float A = 1.f;
    for (int t = 0; t < CLEN; t++) {
        size_t idx = base + (size_t)t * D_;
        A *= g_alpha[idx];
        float h = fmaf(A, carry, g_h[idx]);
        g_h[idx] = h;
        o_out[idx] = out_in[idx] + h;
    }
}

// ---------------------------------------------------------------------------
extern "C" void kernel_launch(void* const* d_in, const int* in_sizes, int n_in,
                              void* d_out, int out_size)
{
    const float* v    = (const float*)d_in[0];
    const float* ctx  = (const float*)d_in[1];
    const float* out  = (const float*)d_in[2];
    const float* alog = (const float*)d_in[3];
    const float* g    = (const float*)d_in[4];
    const float* Wa   = (const float*)d_in[5];
    const float* ba   = (const float*)d_in[6];
    const float* Wb   = (const float*)d_in[7];
    const float* bb   = (const float*)d_in[8];
    const float* Wc   = (const float*)d_in[9];
    const float* bc   = (const float*)d_in[10];

    float* o      = (float*)d_out;
    float* o_v    = o;
    float* o_ctx  = o + (size_t)TOT;
    float* o_out  = o + (size_t)2 * TOT;
    float* o_alog = o + (size_t)3 * TOT;

    static int smem_set = 0;
    if (!smem_set) {
        cudaFuncSetAttribute(gemm_ab_kernel,  cudaFuncAttributeMaxDynamicSharedMemorySize, SMEM_BYTES);
        cudaFuncSetAttribute(gemm_ctx_kernel, cudaFuncAttributeMaxDynamicSharedMemorySize, SMEM_BYTES);
        smem_set = 1;
    }

    cudaMemcpyAsync(o_alog, alog, (size_t)TOT * sizeof(float), cudaMemcpyDeviceToDevice, 0);

    rms_kernel<<<M_, 256>>>(ctx, g);
    gemm_ab_kernel<<<dim3(8, 128), 256, SMEM_BYTES>>>(Wa, Wb, ba, bb);
    scan1_kernel<<<dim3(D_ / 256, NCHUNK, B_), 256>>>(v, o_v);
    scan2_kernel<<<dim3(D_ / 256, B_), 256>>>();
    scan3_out_kernel<<<dim3(D_ / 256, NCHUNK, B_), 256>>>(out, o_out);
    gemm_ctx_kernel<<<dim3(4, 128), 256, SMEM_BYTES>>>(Wc, bc, ctx, o_ctx);
}

// round 7
// speedup vs baseline: 5.1545x; 1.3555x over previous
#include <cuda_runtime.h>
#include <cuda_fp16.h>
#include <math.h>
#include <stdint.h>

#define B_ 4
#define L_ 4096
#define D_ 1024
#define M_ (B_*L_)            // 16384 rows
#define TOT (M_*D_)           // 16777216 elements per tensor
#define NCHUNK 32
#define CLEN (L_/NCHUNK)      // 128
#define KT (D_/16)            // 64 k-tiles of 16

// ---- GEMM tiling: block 128(M) x 256(N), 8 warps 2x4, warp tile 64x64, fp16 ----
#define STAGES 5
#define AST 24                 // halves per A row (16 + 8 pad) -> 48B, conflict-free
#define BST 24                 // halves per B row
#define A_STAGE (128*AST)      // 3072 halves
#define B_STAGE (256*BST)      // 6144 halves
#define STAGE_HALVES (A_STAGE + B_STAGE)        // 9216 (18KB)
#define SMEM_BYTES (STAGES*STAGE_HALVES*2)      // 92160

// ---- scratch (device globals: no runtime allocation allowed) ----
__device__ float  g_alpha[TOT];
__device__ float  g_beta [TOT];
__device__ float  g_h    [TOT];
__device__ __half g_norm16[TOT];
__device__ __half g_h16  [TOT];
__device__ float  g_Aprod[B_*NCHUNK*D_];
__device__ float  g_hend [B_*NCHUNK*D_];
__device__ float  g_carry[B_*NCHUNK*D_];
__device__ __half g_WaT16[D_*D_];
__device__ __half g_WbT16[D_*D_];
__device__ __half g_WcT16[D_*D_];

__device__ __forceinline__ float sigmoidf_(float z) { return 1.f / (1.f + expf(-z)); }
__device__ __forceinline__ float siluf_(float z)    { return z   / (1.f + expf(-z)); }

__device__ __forceinline__ void mma_f16(float c[4],
    uint32_t a0, uint32_t a1, uint32_t a2, uint32_t a3, uint32_t b0, uint32_t b1) {
    asm volatile(
        "mma.sync.aligned.m16n8k16.row.col.f32.f16.f16.f32 "
        "{%0,%1,%2,%3},{%4,%5,%6,%7},{%8,%9},{%0,%1,%2,%3};"
        : "+f"(c[0]), "+f"(c[1]), "+f"(c[2]), "+f"(c[3])
        : "r"(a0), "r"(a1), "r"(a2), "r"(a3), "r"(b0), "r"(b1));
}
__device__ __forceinline__ void cp16(void* dst, const void* src) {
    uint32_t d = (uint32_t)__cvta_generic_to_shared(dst);
    asm volatile("cp.async.cg.shared.global [%0], [%1], 16;" :: "r"(d), "l"(src));
}
#define CP_COMMIT()  asm volatile("cp.async.commit_group;")
#define CP_WAIT3()   asm volatile("cp.async.wait_group 3;")

// ---------------------------------------------------------------------------
// RMS norm -> half output
// ---------------------------------------------------------------------------
__global__ void rms_kernel(const float* __restrict__ ctx, const float* __restrict__ g) {
    int row = blockIdx.x;
    const float* x = ctx + (size_t)row * D_;
    float s = 0.f;
    #pragma unroll
    for (int i = threadIdx.x; i < D_; i += 256) { float v = x[i]; s += v * v; }
    __shared__ float red[8];
    #pragma unroll
    for (int o = 16; o > 0; o >>= 1) s += __shfl_xor_sync(0xffffffffu, s, o);
    if ((threadIdx.x & 31) == 0) red[threadIdx.x >> 5] = s;
    __syncthreads();
    if (threadIdx.x < 8) {
        float t = red[threadIdx.x];
        #pragma unroll
        for (int o = 4; o > 0; o >>= 1) t += __shfl_xor_sync(0xffu, t, o);
        if (threadIdx.x == 0) red[0] = t;
    }
    __syncthreads();
    float inv = rsqrtf(red[0] * (1.f / D_) + 1e-6f);
    __half* y = g_norm16 + (size_t)row * D_;
    for (int i = threadIdx.x; i < D_; i += 256) y[i] = __float2half(x[i] * inv * g[i]);
}

// ---------------------------------------------------------------------------
// Transpose + fp32->fp16 convert of the three weight matrices:
// WT16[n*D + k] = half(W[k*D + n]). grid (32,32,3), block (32,8).
// ---------------------------------------------------------------------------
__global__ void transpose3_kernel(const float* __restrict__ Wa,
                                  const float* __restrict__ Wb,
                                  const float* __restrict__ Wc) {
    __shared__ float t[32][33];
    const float* src = (blockIdx.z == 0) ? Wa : (blockIdx.z == 1) ? Wb : Wc;
    __half* dst = (blockIdx.z == 0) ? g_WaT16 : (blockIdx.z == 1) ? g_WbT16 : g_WcT16;
    int x = blockIdx.x * 32 + threadIdx.x;
    int y0 = blockIdx.y * 32;
    #pragma unroll
    for (int j = 0; j < 32; j += 8)
        t[threadIdx.y + j][threadIdx.x] = src[(size_t)(y0 + threadIdx.y + j) * D_ + x];
    __syncthreads();
    int x2 = blockIdx.y * 32 + threadIdx.x;
    int y2 = blockIdx.x * 32;
    #pragma unroll
    for (int j = 0; j < 32; j += 8)
        dst[(size_t)(y2 + threadIdx.y + j) * D_ + x2] = __float2half(t[threadIdx.x][threadIdx.y + j]);
}

// ---------------------------------------------------------------------------
// fp16 mainloop: acc[4][8][4] for 128x256 tile of A16 @ WT16^T.
// A16 row-major [M,1024] halves; WT16 [1024 n][1024 k] halves (n rows).
// Tiles in smem as [row][16 k] halves, stride 24.
// ---------------------------------------------------------------------------
__device__ __forceinline__ void gemm_core(
    __half* sm, const __half* __restrict__ A16, const __half* __restrict__ WT,
    int m0, int ncol0, float acc[4][8][4])
{
    const int tid = threadIdx.x;

    auto ld_stage = [&](int stage, int kt) {
        const int k0 = kt * 16;
        __half* As = sm + stage * STAGE_HALVES;
        __half* Bs = As + A_STAGE;
        {   // A: 128 rows x 2 chunks of 16B = 256 chunks
            int r = tid >> 1, q = tid & 1;
            cp16(As + r * AST + q * 8,
                 A16 + (size_t)(m0 + r) * D_ + k0 + q * 8);
        }
        #pragma unroll
        for (int i = 0; i < 2; i++) {   // B: 256 rows x 2 chunks = 512
            int idx = tid + i * 256;
            int r = idx >> 1, q = idx & 1;
            cp16(Bs + r * BST + q * 8,
                 WT + (size_t)(ncol0 + r) * D_ + k0 + q * 8);
        }
    };

    const int lane = tid & 31;
    const int gid = lane >> 2, tig = lane & 3;
    const int wid = tid >> 5;
    const int wm = (wid >> 2) * 64;       // 0 / 64
    const int wn = (wid & 3) * 64;        // 0..192

    #pragma unroll
    for (int s = 0; s < STAGES - 1; s++) { ld_stage(s, s); CP_COMMIT(); }

    int s_cur = 0, s_ld = STAGES - 1;
    for (int kt = 0; kt < KT; kt++) {
        CP_WAIT3();
        __syncthreads();

        const __half* as = sm + s_cur * STAGE_HALVES;
        const __half* bs = as + A_STAGE;

        uint32_t af[4][4], bf[8][2];
        #pragma unroll
        for (int mt = 0; mt < 4; mt++) {
            int r = wm + mt * 16 + gid;
            af[mt][0] = *(const uint32_t*)(as + r * AST + 2 * tig);
            af[mt][1] = *(const uint32_t*)(as + (r + 8) * AST + 2 * tig);
            af[mt][2] = *(const uint32_t*)(as + r * AST + 2 * tig + 8);
            af[mt][3] = *(const uint32_t*)(as + (r + 8) * AST + 2 * tig + 8);
        }
        #pragma unroll
        for (int nt = 0; nt < 8; nt++) {
            int col = wn + nt * 8 + gid;
            bf[nt][0] = *(const uint32_t*)(bs + col * BST + 2 * tig);
            bf[nt][1] = *(const uint32_t*)(bs + col * BST + 2 * tig + 8);
        }
        #pragma unroll
        for (int mt = 0; mt < 4; mt++)
            #pragma unroll
            for (int nt = 0; nt < 8; nt++)
                mma_f16(acc[mt][nt], af[mt][0], af[mt][1], af[mt][2], af[mt][3],
                        bf[nt][0], bf[nt][1]);

        __syncthreads();     // all warps done with s_ld's buffer before overwrite

        int nk = kt + STAGES - 1;
        if (nk < KT) ld_stage(s_ld, nk);
        CP_COMMIT();
        if (++s_cur == STAGES) s_cur = 0;
        if (++s_ld == STAGES) s_ld = 0;
    }
}

// ---------------------------------------------------------------------------
// GEMM 1+2 fused: alpha = sigmoid(norm@Wa+ba), beta = silu(norm@Wb+bb)
// grid (8, 128): x<4 -> alpha cols, x>=4 -> beta
// ---------------------------------------------------------------------------
__global__ __launch_bounds__(256, 1) void gemm_ab_kernel(
    const float* __restrict__ ba, const float* __restrict__ bb)
{
    extern __shared__ __half sm[];
    const int m0 = blockIdx.y * 128;
    const bool isA = (blockIdx.x < 4);
    const int ncol0 = (isA ? blockIdx.x : blockIdx.x - 4) * 256;
    const __half* WT  = isA ? g_WaT16 : g_WbT16;
    const float* bias = isA ? ba : bb;
    float* dst        = isA ? g_alpha : g_beta;

    float acc[4][8][4];
    #pragma unroll
    for (int i = 0; i < 4; i++)
        #pragma unroll
        for (int j = 0; j < 8; j++)
            #pragma unroll
            for (int k = 0; k < 4; k++) acc[i][j][k] = 0.f;

    gemm_core(sm, g_norm16, WT, m0, ncol0, acc);

    const int lane = threadIdx.x & 31;
    const int gid = lane >> 2, tig = lane & 3;
    const int wid = threadIdx.x >> 5;
    const int wm = (wid >> 2) * 64, wn = (wid & 3) * 64;
    #pragma unroll
    for (int mt = 0; mt < 4; mt++) {
        #pragma unroll
        for (int nt = 0; nt < 8; nt++) {
            int col = ncol0 + wn + nt * 8 + 2 * tig;
            #pragma unroll
            for (int half = 0; half < 2; half++) {
                int row = m0 + wm + mt * 16 + gid + half * 8;
                float z0 = acc[mt][nt][half*2+0] + bias[col];
                float z1 = acc[mt][nt][half*2+1] + bias[col+1];
                float2 o;
                if (isA) { o.x = sigmoidf_(z0); o.y = sigmoidf_(z1); }
                else     { o.x = siluf_(z0);    o.y = siluf_(z1); }
                *(float2*)(dst + (size_t)row * D_ + col) = o;
            }
        }
    }
}

// ---------------------------------------------------------------------------
// GEMM 3: ctx_out = ctx + silu(h @ Wc + bc). grid (4, 128)
// ---------------------------------------------------------------------------
__global__ __launch_bounds__(256, 1) void gemm_ctx_kernel(
    const float* __restrict__ bc,
    const float* __restrict__ ctx, float* __restrict__ out_ctx)
{
    extern __shared__ __half sm[];
    const int m0 = blockIdx.y * 128;
    const int ncol0 = blockIdx.x * 256;

    float acc[4][8][4];
    #pragma unroll
    for (int i = 0; i < 4; i++)
        #pragma unroll
        for (int j = 0; j < 8; j++)
            #pragma unroll
            for (int k = 0; k < 4; k++) acc[i][j][k] = 0.f;

    gemm_core(sm, g_h16, g_WcT16, m0, ncol0, acc);

    const int lane = threadIdx.x & 31;
    const int gid = lane >> 2, tig = lane & 3;
    const int wid = threadIdx.x >> 5;
    const int wm = (wid >> 2) * 64, wn = (wid & 3) * 64;
    #pragma unroll
    for (int mt = 0; mt < 4; mt++) {
        #pragma unroll
        for (int nt = 0; nt < 8; nt++) {
            int col = ncol0 + wn + nt * 8 + 2 * tig;
            #pragma unroll
            for (int half = 0; half < 2; half++) {
                int row = m0 + wm + mt * 16 + gid + half * 8;
                size_t idx = (size_t)row * D_ + col;
                float2 cc = *(const float2*)(ctx + idx);
                float2 o;
                o.x = cc.x + siluf_(acc[mt][nt][half*2+0] + bc[col]);
                o.y = cc.y + siluf_(acc[mt][nt][half*2+1] + bc[col+1]);
                *(float2*)(out_ctx + idx) = o;
            }
        }
    }
}

// ---------------------------------------------------------------------------
// Chunked scan (fp32 throughout). Pass 1 also emits the v passthrough copy.
// ---------------------------------------------------------------------------
__global__ void scan1_kernel(const float* __restrict__ v, float* __restrict__ o_v) {
    int d = blockIdx.x * blockDim.x + threadIdx.x;
    int cch = blockIdx.y, b = blockIdx.z;
    size_t base = ((size_t)b * L_ + (size_t)cch * CLEN) * D_ + d;
    float h = 0.f, A = 1.f;
    for (int t = 0; t < CLEN; t++) {
        size_t idx = base + (size_t)t * D_;
        float a  = g_alpha[idx];
        float vv = v[idx];
        float ws = sqrtf(fmaxf(1.f - a * a, 1e-6f));
        float x  = vv * g_beta[idx] * ws;
        h = fmaf(a, h, x);
        A *= a;
        g_h[idx] = h;
        o_v[idx] = vv;
    }
    int sidx = (b * NCHUNK + cch) * D_ + d;
    g_hend[sidx] = h; g_Aprod[sidx] = A;
}

__global__ __launch_bounds__(256) void scan2_kernel() {
    int d = blockIdx.x * 256 + threadIdx.x;
    int b = blockIdx.y;
    float Ap[NCHUNK], He[NCHUNK];
    #pragma unroll
    for (int cc = 0; cc < NCHUNK; cc++) {
        int sidx = (b * NCHUNK + cc) * D_ + d;
        Ap[cc] = g_Aprod[sidx];
        He[cc] = g_hend[sidx];
    }
    float carry = 0.f;
    #pragma unroll
    for (int cc = 0; cc < NCHUNK; cc++) {
        g_carry[(b * NCHUNK + cc) * D_ + d] = carry;
        carry = fmaf(Ap[cc], carry, He[cc]);
    }
}

// Pass 3 fused with out_out = out + fetched; also emits half h for GEMM3.
__global__ void scan3_out_kernel(const float* __restrict__ out_in,
                                 float* __restrict__ o_out) {
    int d = blockIdx.x * blockDim.x + threadIdx.x;
    int cch = blockIdx.y, b = blockIdx.z;
    size_t base = ((size_t)b * L_ + (size_t)cch * CLEN) * D_ + d;
    if (cch == 0) {
        for (int t = 0; t < CLEN; t++) {
            size_t idx = base + (size_t)t * D_;
            float h = g_h[idx];
            g_h16[idx] = __float2half(h);
            o_out[idx] = out_in[idx] + h;
        }
        return;
    }
    float carry = g_carry[(b * NCHUNK + cch) * D_ + d];
    float A = 1.f;
    for (int t = 0; t < CLEN; t++) {
        size_t idx = base + (size_t)t * D_;
        A *= g_alpha[idx];
        float h = fmaf(A, carry, g_h[idx]);
        g_h16[idx] = __float2half(h);
        o_out[idx] = out_in[idx] + h;
    }
}

// ---------------------------------------------------------------------------
extern "C" void kernel_launch(void* const* d_in, const int* in_sizes, int n_in,
                              void* d_out, int out_size)
{
    const float* v    = (const float*)d_in[0];
    const float* ctx  = (const float*)d_in[1];
    const float* out  = (const float*)d_in[2];
    const float* alog = (const float*)d_in[3];
    const float* g    = (const float*)d_in[4];
    const float* Wa   = (const float*)d_in[5];
    const float* ba   = (const float*)d_in[6];
    const float* Wb   = (const float*)d_in[7];
    const float* bb   = (const float*)d_in[8];
    const float* Wc   = (const float*)d_in[9];
    const float* bc   = (const float*)d_in[10];

    float* o      = (float*)d_out;
    float* o_v    = o;
    float* o_ctx  = o + (size_t)TOT;
    float* o_out  = o + (size_t)2 * TOT;
    float* o_alog = o + (size_t)3 * TOT;

    static int smem_set = 0;
    if (!smem_set) {
        cudaFuncSetAttribute(gemm_ab_kernel,  cudaFuncAttributeMaxDynamicSharedMemorySize, SMEM_BYTES);
        cudaFuncSetAttribute(gemm_ctx_kernel, cudaFuncAttributeMaxDynamicSharedMemorySize, SMEM_BYTES);
        smem_set = 1;
    }

    cudaMemcpyAsync(o_alog, alog, (size_t)TOT * sizeof(float), cudaMemcpyDeviceToDevice, 0);

    transpose3_kernel<<<dim3(32, 32, 3), dim3(32, 8)>>>(Wa, Wb, Wc);
    rms_kernel<<<M_, 256>>>(ctx, g);
    gemm_ab_kernel<<<dim3(8, 128), 256, SMEM_BYTES>>>(ba, bb);
    scan1_kernel<<<dim3(D_ / 256, NCHUNK, B_), 256>>>(v, o_v);
    scan2_kernel<<<dim3(D_ / 256, B_), 256>>>();
    scan3_out_kernel<<<dim3(D_ / 256, NCHUNK, B_), 256>>>(out, o_out);
    gemm_ctx_kernel<<<dim3(4, 128), 256, SMEM_BYTES>>>(bc, ctx, o_ctx);
}